// round 7
// baseline (speedup 1.0000x reference)
#include <cuda_runtime.h>
#include <cuda_bf16.h>
#include <cstdint>
#include <math.h>

#define B_  128
#define F_  1024
#define W_  32
#define H_  64
#define G_  256
#define NCH 64           // total k16 chunks
#define NKQ 4            // k-split across CTAs

#define AP   40          // A smem row pitch (bf16): conflict-free ldmatrix
#define OALQ (128 * AP)  // A-lo offset within slice (bf16 units)
#define SMEM_GEMM (2 * 128 * AP * 2)   // 20480 B

using u64 = unsigned long long;

// B pre-packed into mma-fragment layout: [chunk][ntile][lane] -> uint4{bh0,bh1,bl0,bl1}
__device__ uint4 g_wxp[NCH * 32 * 32];
// Split-K partials: [kq][b][t][g]  (16 MB)
__device__ float g_part[NKQ * B_ * W_ * G_];

__device__ __forceinline__ uint32_t smem_u32(const void* p) {
    return (uint32_t)__cvta_generic_to_shared(p);
}
__device__ __forceinline__ void ldm4t(uint32_t* r, uint32_t addr) {
    asm volatile("ldmatrix.sync.aligned.m8n8.x4.trans.shared.b16 {%0,%1,%2,%3}, [%4];"
                 : "=r"(r[0]), "=r"(r[1]), "=r"(r[2]), "=r"(r[3]) : "r"(addr));
}
__device__ __forceinline__ void mma_bf16(float* d, const uint32_t* a, uint32_t b0, uint32_t b1) {
    asm volatile("mma.sync.aligned.m16n8k16.row.col.f32.bf16.bf16.f32 "
                 "{%0,%1,%2,%3}, {%4,%5,%6,%7}, {%8,%9}, {%0,%1,%2,%3};"
                 : "+f"(d[0]), "+f"(d[1]), "+f"(d[2]), "+f"(d[3])
                 : "r"(a[0]), "r"(a[1]), "r"(a[2]), "r"(a[3]), "r"(b0), "r"(b1));
}
__device__ __forceinline__ u64 fma2(u64 a, u64 b, u64 c) {
    u64 d; asm("fma.rn.f32x2 %0, %1, %2, %3;" : "=l"(d) : "l"(a), "l"(b), "l"(c)); return d;
}
__device__ __forceinline__ u64 add2(u64 a, u64 b) {
    u64 d; asm("add.rn.f32x2 %0, %1, %2;" : "=l"(d) : "l"(a), "l"(b)); return d;
}
__device__ __forceinline__ u64 pack2(float lo, float hi) {
    u64 d; asm("mov.b64 %0, {%1, %2};" : "=l"(d)
               : "r"(__float_as_uint(lo)), "r"(__float_as_uint(hi)));
    return d;
}
__device__ __forceinline__ float2 unpack2(u64 a) {
    unsigned lo, hi; asm("mov.b64 {%0, %1}, %2;" : "=r"(lo), "=r"(hi) : "l"(a));
    return make_float2(__uint_as_float(lo), __uint_as_float(hi));
}
__device__ __forceinline__ uint32_t packbf(float a, float b) {
    uint32_t r; asm("cvt.rn.bf16x2.f32 %0, %1, %2;" : "=r"(r) : "f"(b), "f"(a));
    return r;
}

// ---------------------------------------------------------------------------
// Pre-kernel: Wx fp32 -> packed bf16 hi/lo mma B-fragments.
// ---------------------------------------------------------------------------
extern "C" __global__ void __launch_bounds__(256)
conv_wx_kernel(const float* __restrict__ Wx)
{
    int gid   = blockIdx.x * 256 + threadIdx.x;
    int lane  = gid & 31;
    int tile  = (gid >> 5) & 31;
    int chunk = gid >> 10;
    int n  = tile * 8 + (lane >> 2);
    int k0 = chunk * 16 + 2 * (lane & 3);

    float w00 = Wx[(size_t)k0 * G_ + n];
    float w01 = Wx[(size_t)(k0 + 1) * G_ + n];
    float w10 = Wx[(size_t)(k0 + 8) * G_ + n];
    float w11 = Wx[(size_t)(k0 + 9) * G_ + n];

    float h00 = __bfloat162float(__float2bfloat16(w00));
    float h01 = __bfloat162float(__float2bfloat16(w01));
    float h10 = __bfloat162float(__float2bfloat16(w10));
    float h11 = __bfloat162float(__float2bfloat16(w11));

    uint4 v;
    v.x = packbf(h00, h01);
    v.y = packbf(h10, h11);
    v.z = packbf(w00 - h00, w01 - h01);
    v.w = packbf(w10 - h10, w11 - h11);
    g_wxp[gid] = v;
}

// ---------------------------------------------------------------------------
// GEMM kernel: grid (128 batches, 4 k-quarters), 256 threads (8 warps).
//  Partial[kq][b][t][g] = sum_{f in quarter kq} x[b,f,t] * Wx[f,g]
//  (softmax over the size-1 axis == 1 -> attention branch is dead code)
//  Warp w = n-group (n0 = 32w), m32 x n32, k256 in 16 chunks.
//  A slice staged in two k128 halves (20 KB smem). B frags via direct
//  LDG.128 from packed array. 3 CTAs/SM hide all latencies.
// ---------------------------------------------------------------------------
extern "C" __global__ void __launch_bounds__(256, 3)
xproj_gemm(const float* __restrict__ x)
{
    extern __shared__ __align__(16) __nv_bfloat16 sA[];   // hi [0,OALQ), lo [OALQ,2*OALQ)

    const int b    = blockIdx.x;
    const int kq   = blockIdx.y;
    const int tid  = threadIdx.x;
    const int w    = tid >> 5;
    const int lane = tid & 31;

    const float* xb = x + (size_t)b * F_ * W_ + (size_t)kq * 256 * W_;

    float acc[2][4][4];
#pragma unroll
    for (int mt = 0; mt < 2; ++mt)
#pragma unroll
        for (int j = 0; j < 4; ++j)
#pragma unroll
            for (int i = 0; i < 4; ++i) acc[mt][j][i] = 0.f;

    const int lr = lane & 7, lg = lane >> 3;
    const int akq = (lg & 2) ? (8 + lr) : lr;
    const int amo = (lg & 1) ? 8 : 0;

    const uint4* bsrc = g_wxp + ((size_t)(4 * w) * 32) + lane;

    for (int s = 0; s < 2; ++s) {
        // ---- stage k128 A slice (hi/lo) ----
        {
            const int rbase = tid >> 4;            // 0..15
            const int tc    = (tid & 15) * 2;
#pragma unroll
            for (int seg = 0; seg < 8; ++seg) {
                int fl = rbase + 16 * seg;
                float2 v = *(const float2*)(xb + (size_t)(s * 128 + fl) * W_ + tc);
                __nv_bfloat16 h0 = __float2bfloat16(v.x);
                __nv_bfloat16 h1 = __float2bfloat16(v.y);
                __nv_bfloat16 l0 = __float2bfloat16(v.x - __bfloat162float(h0));
                __nv_bfloat16 l1 = __float2bfloat16(v.y - __bfloat162float(h1));
                *(__nv_bfloat162*)(sA + fl * AP + tc)        = __nv_bfloat162{h0, h1};
                *(__nv_bfloat162*)(sA + OALQ + fl * AP + tc) = __nv_bfloat162{l0, l1};
            }
        }
        __syncthreads();

        for (int c = 0; c < 8; ++c) {
            int ch = kq * 16 + s * 8 + c;
            uint4 bq[4];
#pragma unroll
            for (int j = 0; j < 4; ++j)
                bq[j] = bsrc[(size_t)ch * 1024 + (size_t)j * 32];

            int fb = c * 16 + akq;
            uint32_t ah[2][4], al[2][4];
#pragma unroll
            for (int mt = 0; mt < 2; ++mt) {
                ldm4t(ah[mt], smem_u32(sA + fb * AP + 16 * mt + amo));
                ldm4t(al[mt], smem_u32(sA + OALQ + fb * AP + 16 * mt + amo));
            }
#pragma unroll
            for (int j = 0; j < 4; ++j) {
#pragma unroll
                for (int mt = 0; mt < 2; ++mt) {
                    mma_bf16(acc[mt][j], ah[mt], bq[j].x, bq[j].y);
                    mma_bf16(acc[mt][j], ah[mt], bq[j].z, bq[j].w);
                    mma_bf16(acc[mt][j], al[mt], bq[j].x, bq[j].y);
                }
            }
        }
        __syncthreads();
    }

    // ---- write partials (coalesced float2) ----
    float* op = g_part + ((size_t)(kq * B_ + b) * W_) * G_;
    const int r0 = lane >> 2, c0 = 2 * (lane & 3);
#pragma unroll
    for (int mt = 0; mt < 2; ++mt)
#pragma unroll
        for (int j = 0; j < 4; ++j) {
            int n = 32 * w + 8 * j;
            *(float2*)(op + (16 * mt + r0) * G_ + n + c0)     = make_float2(acc[mt][j][0], acc[mt][j][1]);
            *(float2*)(op + (16 * mt + r0 + 8) * G_ + n + c0) = make_float2(acc[mt][j][2], acc[mt][j][3]);
        }
}

// ---------------------------------------------------------------------------
// LSTM kernel: grid 128, 256 threads. Reduce 4 partials into smem gate
// tile, then run the recurrence. Output per step = CELL state.
// ---------------------------------------------------------------------------
extern "C" __global__ void __launch_bounds__(256, 1)
lstm_kernel(const float* __restrict__ Wh, const float* __restrict__ b_lstm,
            float* __restrict__ out)
{
    __shared__ __align__(16) float xp[W_ * G_];    // 32 KB gate tile
    __shared__ __align__(16) float h_s[2][H_];

    const int b   = blockIdx.x;
    const int tid = threadIdx.x;
    const int w   = tid >> 5;
    const int lane = tid & 31;

    // ---- reduce split-K partials ----
    {
        const float* p0 = g_part + (size_t)(0 * B_ + b) * W_ * G_;
        const float* p1 = g_part + (size_t)(1 * B_ + b) * W_ * G_;
        const float* p2 = g_part + (size_t)(2 * B_ + b) * W_ * G_;
        const float* p3 = g_part + (size_t)(3 * B_ + b) * W_ * G_;
#pragma unroll
        for (int i = tid * 4; i < W_ * G_; i += 256 * 4) {
            float4 a0 = *(const float4*)(p0 + i);
            float4 a1 = *(const float4*)(p1 + i);
            float4 a2 = *(const float4*)(p2 + i);
            float4 a3 = *(const float4*)(p3 + i);
            *(float4*)(xp + i) = make_float4(a0.x + a1.x + a2.x + a3.x,
                                             a0.y + a1.y + a2.y + a3.y,
                                             a0.z + a1.z + a2.z + a3.z,
                                             a0.w + a1.w + a2.w + a3.w);
        }
    }

    const int q   = lane >> 3;
    const int r   = lane & 7;
    const int idx = 8 * w + r;
    const int col = q * 64 + idx;

    u64 whp[H_ / 2];
#pragma unroll
    for (int m = 0; m < H_ / 2; ++m)
        whp[m] = pack2(Wh[(2 * m) * G_ + col], Wh[(2 * m + 1) * G_ + col]);
    const float bj = b_lstm[col];

    if (tid < H_) h_s[0][tid] = 0.f;
    float c_st = 0.f;
    float* ob = out + (size_t)b * W_ * H_;
    __syncthreads();

    int p = 0;
    for (int t = 0; t < W_; ++t) {
        const u64* hp = (const u64*)h_s[p];
        u64 a0 = 0ull, a1 = 0ull, a2 = 0ull, a3 = 0ull;
#pragma unroll
        for (int m = 0; m < H_ / 2; m += 4) {
            a0 = fma2(hp[m + 0], whp[m + 0], a0);
            a1 = fma2(hp[m + 1], whp[m + 1], a1);
            a2 = fma2(hp[m + 2], whp[m + 2], a2);
            a3 = fma2(hp[m + 3], whp[m + 3], a3);
        }
        float2 s2 = unpack2(add2(add2(a0, a1), add2(a2, a3)));
        float g = s2.x + s2.y + xp[t * G_ + col] + bj;

        float sc  = (q == 2) ? -2.f : -1.f;
        float e   = __expf(sc * g);
        float num = (q == 2) ? (1.f - e) : 1.f;
        float act = __fdividef(num, 1.f + e);

        float ai = __shfl_sync(0xffffffffu, act, r);
        float af = __shfl_sync(0xffffffffu, act, 8 + r);
        float ag = __shfl_sync(0xffffffffu, act, 16 + r);
        float ao = __shfl_sync(0xffffffffu, act, 24 + r);

        c_st = fmaf(af, c_st, ai * ag);
        float e2 = __expf(-2.f * c_st);
        float th = __fdividef(1.f - e2, 1.f + e2);

        if (q == 0) {
            h_s[p ^ 1][idx] = ao * th;
            ob[t * H_ + idx] = c_st;              // reference emits the CELL state
        }
        p ^= 1;
        __syncthreads();
    }
}

// ---------------------------------------------------------------------------
extern "C" void kernel_launch(void* const* d_in, const int* in_sizes, int n_in,
                              void* d_out, int out_size)
{
    const float* x      = (const float*)d_in[0];
    const float* Wx     = (const float*)d_in[6];
    const float* Wh     = (const float*)d_in[7];
    const float* b_lstm = (const float*)d_in[8];
    float*       out    = (float*)d_out;

    cudaFuncSetAttribute(xproj_gemm, cudaFuncAttributeMaxDynamicSharedMemorySize, SMEM_GEMM);

    conv_wx_kernel<<<256, 256>>>(Wx);
    xproj_gemm<<<dim3(B_, NKQ), 256, SMEM_GEMM>>>(x);
    lstm_kernel<<<B_, 256>>>(Wh, b_lstm, out);
}